// round 1
// baseline (speedup 1.0000x reference)
#include <cuda_runtime.h>
#include <cstdint>

#define NB 16
#define NS 196
#define NHEADS 8
#define NDH 64
#define NHID 512
#define NM (NB*NS)                       // 3136 rows for projections
#define BUF_ELEMS (NB*NHEADS*NS*NDH)     // 1,605,632 floats per buffer

// Scratch (no allocations allowed): Q,K,V,G in [b,h,s,d] layout, ~6.4MB each.
__device__ float g_Q[BUF_ELEMS];
__device__ float g_K[BUF_ELEMS];
__device__ float g_V[BUF_ELEMS];
__device__ float g_G[BUF_ELEMS];

// ---------------------------------------------------------------------------
// Kernel 1: fused QKVG projections.  y = x @ W + b, output in [b,h,s,d].
// 128x128 tile, BK=8, 256 threads, 8x8 per-thread microtile.
// grid = (N/128=4, ceil(M/128)=25, 4 weights)
// ---------------------------------------------------------------------------
__global__ __launch_bounds__(256) void proj_kernel(
    const float* __restrict__ X,
    const float* __restrict__ W0, const float* __restrict__ b0,
    const float* __restrict__ W1, const float* __restrict__ b1,
    const float* __restrict__ W2, const float* __restrict__ b2,
    const float* __restrict__ W3, const float* __restrict__ b3)
{
    const float* W;
    const float* bias;
    float* out;
    switch (blockIdx.z) {
        case 0:  W = W0; bias = b0; out = g_Q; break;
        case 1:  W = W1; bias = b1; out = g_K; break;
        case 2:  W = W2; bias = b2; out = g_V; break;
        default: W = W3; bias = b3; out = g_G; break;
    }

    __shared__ float As[8][128];
    __shared__ float Bs[8][128];

    const int m0 = blockIdx.y * 128;
    const int n0 = blockIdx.x * 128;
    const int tid = threadIdx.x;
    const int ty = tid >> 4, tx = tid & 15;
    const int arow = tid >> 1, acol = (tid & 1) * 4;
    const int brow = tid >> 5, bcol = (tid & 31) * 4;

    float acc[8][8];
#pragma unroll
    for (int i = 0; i < 8; ++i)
#pragma unroll
        for (int j = 0; j < 8; ++j) acc[i][j] = 0.f;

    for (int k0 = 0; k0 < NHID; k0 += 8) {
        float4 av = make_float4(0.f, 0.f, 0.f, 0.f);
        const int gm = m0 + arow;
        if (gm < NM)
            av = *(const float4*)(X + (size_t)gm * NHID + k0 + acol);
        As[acol + 0][arow] = av.x;
        As[acol + 1][arow] = av.y;
        As[acol + 2][arow] = av.z;
        As[acol + 3][arow] = av.w;
        *(float4*)&Bs[brow][bcol] =
            *(const float4*)(W + (size_t)(k0 + brow) * NHID + n0 + bcol);
        __syncthreads();

#pragma unroll
        for (int kk = 0; kk < 8; ++kk) {
            float a[8], bb[8];
            *(float4*)(a)      = *(float4*)&As[kk][ty * 8];
            *(float4*)(a + 4)  = *(float4*)&As[kk][ty * 8 + 4];
            *(float4*)(bb)     = *(float4*)&Bs[kk][tx * 8];
            *(float4*)(bb + 4) = *(float4*)&Bs[kk][tx * 8 + 4];
#pragma unroll
            for (int i = 0; i < 8; ++i)
#pragma unroll
                for (int j = 0; j < 8; ++j)
                    acc[i][j] += a[i] * bb[j];
        }
        __syncthreads();
    }

#pragma unroll
    for (int i = 0; i < 8; ++i) {
        const int m = m0 + ty * 8 + i;
        if (m >= NM) continue;
        const int bI = m / NS;
        const int sI = m - bI * NS;
#pragma unroll
        for (int j = 0; j < 8; ++j) {
            const int n = n0 + tx * 8 + j;
            const int h = n >> 6, d = n & 63;
            out[(((size_t)bI * NHEADS + h) * NS + sI) * NDH + d] =
                acc[i][j] + bias[n];
        }
    }
}

// ---------------------------------------------------------------------------
// Kernel 2: attention with geometric bias.
// One block = (b, h, tile of TQ=14 queries). 256 threads.
//   Phase 1: s[qi][k] = scale*(q.k) + (g.rpe) + mask   (half-warp per k, f4 dots)
//   Phase 2: softmax per qi (one warp per qi), write probs
//   Phase 3: one V pass computing ctx for all 14 queries
// K tile cached in SMEM (50KB) so K is read from L2 once per block, not per q.
// ---------------------------------------------------------------------------
#define TQ 14
#define ATTN_SMEM_FLOATS (NS*NDH + TQ*NDH + TQ*NDH + TQ*NS + NS)
#define ATTN_SMEM_BYTES  (ATTN_SMEM_FLOATS * 4)

__global__ __launch_bounds__(256) void attn_kernel(
    const float* __restrict__ rpe, const float* __restrict__ mask,
    float* __restrict__ out_ctx, float* __restrict__ out_probs,
    int write_probs)
{
    extern __shared__ float smem[];
    float* Ks    = smem;                  // [196][64] = 12544
    float* qsm   = Ks + NS * NDH;         // [14][64]  = 896 (pre-scaled)
    float* gsm   = qsm + TQ * NDH;        // [14][64]  = 896
    float* sc    = gsm + TQ * NDH;        // [14][196] = 2744
    float* msk   = sc + TQ * NS;          // [196]
    float* cpart = smem;                  // phase-3 alias over Ks region

    const int q0 = blockIdx.x * TQ;
    const int h  = blockIdx.y;
    const int b  = blockIdx.z;
    const int bh = b * NHEADS + h;
    const int tid  = threadIdx.x;
    const int warp = tid >> 5;
    const int lane = tid & 31;

    // ---- stage tiles ----
    {
        const float4* Kb = (const float4*)(g_K + (size_t)bh * NS * NDH);
        float4* K4 = (float4*)Ks;
        for (int j = tid; j < NS * NDH / 4; j += 256) K4[j] = Kb[j];
        const float* Qb = g_Q + ((size_t)bh * NS + q0) * NDH;
        const float* Gb = g_G + ((size_t)bh * NS + q0) * NDH;
        for (int j = tid; j < TQ * NDH; j += 256) {
            qsm[j] = Qb[j] * 0.125f;   // 1/sqrt(64)
            gsm[j] = Gb[j];
        }
        if (tid < NS) msk[tid] = mask[b * NS + tid];
    }
    __syncthreads();

    // ---- phase 1: scores. half-warp (16 lanes, float4) per k; 2 k per warp/step
    const int hh = lane >> 4;    // which half
    const int hl = lane & 15;    // lane within half
    const float* rbase = rpe + ((size_t)bh * NS + q0) * NS * NDH;

    for (int qi = 0; qi < TQ; ++qi) {
        const float4 qv = *(const float4*)&qsm[qi * NDH + hl * 4];
        const float4 gv = *(const float4*)&gsm[qi * NDH + hl * 4];
        const float* rrow = rbase + (size_t)qi * NS * NDH;
#pragma unroll
        for (int i = 0; i < 13; ++i) {
            const int k = 2 * warp + hh + 16 * i;
            if (k < NS) {   // uniform across the warp (k, k+1 pair)
                const float4 kv = *(const float4*)&Ks[k * NDH + hl * 4];
                const float4 rv = *(const float4*)(rrow + (size_t)k * NDH + hl * 4);
                float acc = qv.x * kv.x + qv.y * kv.y + qv.z * kv.z + qv.w * kv.w
                          + gv.x * rv.x + gv.y * rv.y + gv.z * rv.z + gv.w * rv.w;
                acc += __shfl_xor_sync(0xffffffffu, acc, 8);
                acc += __shfl_xor_sync(0xffffffffu, acc, 4);
                acc += __shfl_xor_sync(0xffffffffu, acc, 2);
                acc += __shfl_xor_sync(0xffffffffu, acc, 1);
                if (hl == 0) sc[qi * NS + k] = acc + msk[k];
            }
        }
    }
    __syncthreads();

    // ---- phase 2: softmax (one warp per query row) + probs write
    for (int qi = warp; qi < TQ; qi += 8) {
        float m = -1e30f;
        for (int j = lane; j < NS; j += 32) m = fmaxf(m, sc[qi * NS + j]);
#pragma unroll
        for (int o = 16; o; o >>= 1) m = fmaxf(m, __shfl_xor_sync(0xffffffffu, m, o));
        float sum = 0.f;
        for (int j = lane; j < NS; j += 32) {
            const float e = __expf(sc[qi * NS + j] - m);
            sc[qi * NS + j] = e;
            sum += e;
        }
#pragma unroll
        for (int o = 16; o; o >>= 1) sum += __shfl_xor_sync(0xffffffffu, sum, o);
        const float inv = 1.0f / sum;
        const size_t pb = ((size_t)bh * NS + q0 + qi) * NS;
        for (int j = lane; j < NS; j += 32) {
            const float p = sc[qi * NS + j] * inv;
            sc[qi * NS + j] = p;
            if (write_probs) out_probs[pb + j] = p;
        }
    }
    __syncthreads();

    // ---- phase 3: ctx = probs @ V, all TQ queries in one V pass
    const int d = tid & 63;
    const int g = tid >> 6;   // 0..3, k-groups
    const float* Vb = g_V + (size_t)bh * NS * NDH;
    float acc[TQ];
#pragma unroll
    for (int qi = 0; qi < TQ; ++qi) acc[qi] = 0.f;
#pragma unroll 7
    for (int it = 0; it < 49; ++it) {
        const int k = g + it * 4;
        const float v = Vb[(size_t)k * NDH + d];
#pragma unroll
        for (int qi = 0; qi < TQ; ++qi)
            acc[qi] += sc[qi * NS + k] * v;
    }
#pragma unroll
    for (int qi = 0; qi < TQ; ++qi)
        cpart[(qi * 4 + g) * NDH + d] = acc[qi];
    __syncthreads();

    for (int t = tid; t < TQ * NDH; t += 256) {
        const int qi = t >> 6, dd = t & 63;
        const float c = cpart[qi * 256 + dd]       + cpart[qi * 256 + 64 + dd]
                      + cpart[qi * 256 + 128 + dd] + cpart[qi * 256 + 192 + dd];
        // ctx layout: [B, S, NH, DH]
        out_ctx[(((size_t)b * NS + q0 + qi) * NHEADS + h) * NDH + dd] = c;
    }
}

// ---------------------------------------------------------------------------
// Launch. Inputs: hidden, rpe, mask, Wq,bq, Wk,bk, Wv,bv, Wg,bg.
// Output assumed = concat(ctx.flat, probs.flat); probs write guarded by out_size.
// ---------------------------------------------------------------------------
extern "C" void kernel_launch(void* const* d_in, const int* in_sizes, int n_in,
                              void* d_out, int out_size)
{
    const float* hidden = (const float*)d_in[0];
    const float* rpe    = (const float*)d_in[1];
    const float* mask   = (const float*)d_in[2];
    const float* Wq = (const float*)d_in[3];
    const float* bq = (const float*)d_in[4];
    const float* Wk = (const float*)d_in[5];
    const float* bk = (const float*)d_in[6];
    const float* Wv = (const float*)d_in[7];
    const float* bv = (const float*)d_in[8];
    const float* Wg = (const float*)d_in[9];
    const float* bg = (const float*)d_in[10];

    float* out = (float*)d_out;
    const size_t ctx_elems   = (size_t)NB * NS * NHID;          // 1,605,632
    const size_t probs_elems = (size_t)NB * NHEADS * NS * NS;   // 4,917,248
    const int write_probs = ((size_t)out_size >= ctx_elems + probs_elems) ? 1 : 0;
    float* out_probs = out + ctx_elems;

    proj_kernel<<<dim3(4, 25, 4), 256>>>(hidden, Wq, bq, Wk, bk, Wv, bv, Wg, bg);

    cudaFuncSetAttribute(attn_kernel,
                         cudaFuncAttributeMaxDynamicSharedMemorySize,
                         ATTN_SMEM_BYTES);
    attn_kernel<<<dim3(NS / TQ, NHEADS, NB), 256, ATTN_SMEM_BYTES>>>(
        rpe, mask, out, out_probs, write_probs);
}

// round 2
// speedup vs baseline: 1.1968x; 1.1968x over previous
#include <cuda_runtime.h>
#include <cstdint>

#define NB 16
#define NS 196
#define NHEADS 8
#define NDH 64
#define NHID 512
#define NM (NB*NS)                       // 3136 rows for projections
#define BUF_ELEMS (NB*NHEADS*NS*NDH)     // 1,605,632 floats per buffer

// Scratch (no allocations allowed): Q,K,V,G in [b,h,s,d] layout, ~6.4MB each.
__device__ float g_Q[BUF_ELEMS];
__device__ float g_K[BUF_ELEMS];
__device__ float g_V[BUF_ELEMS];
__device__ float g_G[BUF_ELEMS];

// ---- packed f32x2 helpers (sm_100+; doubles fp32 FMA throughput) ----
__device__ __forceinline__ unsigned long long pack_dup(float x) {
    unsigned long long r;
    asm("mov.b64 %0, {%1, %1};" : "=l"(r) : "f"(x));
    return r;
}
__device__ __forceinline__ void fma2(unsigned long long& d,
                                     unsigned long long a,
                                     unsigned long long b) {
    asm("fma.rn.f32x2 %0, %1, %2, %0;" : "+l"(d) : "l"(a), "l"(b));
}
__device__ __forceinline__ void unpack2(unsigned long long v, float& lo, float& hi) {
    asm("mov.b64 {%0, %1}, %2;" : "=f"(lo), "=f"(hi) : "l"(v));
}

// ---------------------------------------------------------------------------
// Kernel 1: fused QKVG projections.  y = x @ W + b, output in [b,h,s,d].
// 128x128 tile, BK=8, 256 threads, 8x8 per-thread microtile, f32x2 FMA.
// grid = (4, 25, 4)
// ---------------------------------------------------------------------------
__global__ __launch_bounds__(256) void proj_kernel(
    const float* __restrict__ X,
    const float* __restrict__ W0, const float* __restrict__ b0,
    const float* __restrict__ W1, const float* __restrict__ b1,
    const float* __restrict__ W2, const float* __restrict__ b2,
    const float* __restrict__ W3, const float* __restrict__ b3)
{
    const float* W;
    const float* bias;
    float* out;
    switch (blockIdx.z) {
        case 0:  W = W0; bias = b0; out = g_Q; break;
        case 1:  W = W1; bias = b1; out = g_K; break;
        case 2:  W = W2; bias = b2; out = g_V; break;
        default: W = W3; bias = b3; out = g_G; break;
    }

    __shared__ float As[8][128];
    __shared__ float Bs[8][128];

    const int m0 = blockIdx.y * 128;
    const int n0 = blockIdx.x * 128;
    const int tid = threadIdx.x;
    const int ty = tid >> 4, tx = tid & 15;
    const int arow = tid >> 1, acol = (tid & 1) * 4;
    const int brow = tid >> 5, bcol = (tid & 31) * 4;

    unsigned long long acc2[8][4];
#pragma unroll
    for (int i = 0; i < 8; ++i)
#pragma unroll
        for (int j = 0; j < 4; ++j) acc2[i][j] = 0ull;

    for (int k0 = 0; k0 < NHID; k0 += 8) {
        float4 av = make_float4(0.f, 0.f, 0.f, 0.f);
        const int gm = m0 + arow;
        if (gm < NM)
            av = *(const float4*)(X + (size_t)gm * NHID + k0 + acol);
        As[acol + 0][arow] = av.x;
        As[acol + 1][arow] = av.y;
        As[acol + 2][arow] = av.z;
        As[acol + 3][arow] = av.w;
        *(float4*)&Bs[brow][bcol] =
            *(const float4*)(W + (size_t)(k0 + brow) * NHID + n0 + bcol);
        __syncthreads();

#pragma unroll
        for (int kk = 0; kk < 8; ++kk) {
            float a[8];
            *(float4*)(a)     = *(float4*)&As[kk][ty * 8];
            *(float4*)(a + 4) = *(float4*)&As[kk][ty * 8 + 4];
            unsigned long long b2[4];
#pragma unroll
            for (int j = 0; j < 4; ++j)
                b2[j] = *(const unsigned long long*)&Bs[kk][tx * 8 + 2 * j];
#pragma unroll
            for (int i = 0; i < 8; ++i) {
                const unsigned long long a2 = pack_dup(a[i]);
#pragma unroll
                for (int j = 0; j < 4; ++j)
                    fma2(acc2[i][j], a2, b2[j]);
            }
        }
        __syncthreads();
    }

#pragma unroll
    for (int i = 0; i < 8; ++i) {
        const int m = m0 + ty * 8 + i;
        if (m >= NM) continue;
        const int bI = m / NS;
        const int sI = m - bI * NS;
#pragma unroll
        for (int j = 0; j < 4; ++j) {
            float lo, hi;
            unpack2(acc2[i][j], lo, hi);
            const int n_lo = n0 + tx * 8 + 2 * j;
            const int h_lo = n_lo >> 6, d_lo = n_lo & 63;
            out[(((size_t)bI * NHEADS + h_lo) * NS + sI) * NDH + d_lo] =
                lo + bias[n_lo];
            const int n_hi = n_lo + 1;
            const int h_hi = n_hi >> 6, d_hi = n_hi & 63;
            out[(((size_t)bI * NHEADS + h_hi) * NS + sI) * NDH + d_hi] =
                hi + bias[n_hi];
        }
    }
}

// ---------------------------------------------------------------------------
// Kernel 2: attention with geometric bias, streaming formulation.
// One block = (b, h, tile of TQ=14 queries). 256 threads, ~19KB smem.
// Phase 1: warp computes 8 k's per step: lane=(k within 8, sub d-group of 4),
//          fuses q.K (K from L2) + g.rpe (DRAM stream) in one pass,
//          reduction = 2 shuffles per 8 k's.
// Phase 2: softmax per query row (one warp each) + probs write.
// Phase 3: ctx: thread owns (d, qi-subset); V from L2; no reduction.
// ---------------------------------------------------------------------------
#define TQ 14
#define SP 200   // score row pitch (padded)

__global__ __launch_bounds__(256) void attn_kernel(
    const float* __restrict__ rpe, const float* __restrict__ mask,
    float* __restrict__ out_ctx, float* __restrict__ out_probs,
    int write_probs)
{
    __shared__ float qsm[TQ * NDH];   // pre-scaled q
    __shared__ float gsm[TQ * NDH];
    __shared__ float sc[TQ * SP];
    __shared__ float msk[NS];

    const int q0 = blockIdx.x * TQ;
    const int h  = blockIdx.y;
    const int b  = blockIdx.z;
    const int bh = b * NHEADS + h;
    const int tid  = threadIdx.x;
    const int warp = tid >> 5;
    const int lane = tid & 31;

    // ---- stage q, g, mask ----
    {
        const float* Qb = g_Q + ((size_t)bh * NS + q0) * NDH;
        const float* Gb = g_G + ((size_t)bh * NS + q0) * NDH;
        for (int j = tid; j < TQ * NDH; j += 256) {
            qsm[j] = Qb[j] * 0.125f;   // 1/sqrt(64)
            gsm[j] = Gb[j];
        }
        if (tid < NS) msk[tid] = mask[b * NS + tid];
    }
    __syncthreads();

    // ---- phase 1: scores ----
    const int kk  = lane >> 2;   // 0..7: k within the 8-group
    const int sub = lane & 3;    // 0..3: d-group
    const float* Kbh = g_K + (size_t)bh * NS * NDH;
    const float* rb  = rpe + ((size_t)bh * NS + q0) * (size_t)NS * NDH;

    const int NTASK = TQ * 25;   // 25 groups of 8 k (last partial)
    for (int task = warp; task < NTASK; task += 8) {
        const int qi = task / 25;
        const int kg = task - qi * 25;
        const int k  = kg * 8 + kk;
        const bool valid = (k < NS);
        const float* rrow = rb  + ((size_t)qi * NS + k) * NDH;
        const float* krow = Kbh + (size_t)k * NDH;

        float acc = 0.f;
#pragma unroll
        for (int j = 0; j < 4; ++j) {
            const int qd = (sub + 4 * j) * 4;
            float4 rv = make_float4(0.f, 0.f, 0.f, 0.f);
            float4 kv = make_float4(0.f, 0.f, 0.f, 0.f);
            if (valid) {
                rv = *(const float4*)(rrow + qd);
                kv = *(const float4*)(krow + qd);
            }
            const float4 gq = *(const float4*)&gsm[qi * NDH + qd];
            const float4 qq = *(const float4*)&qsm[qi * NDH + qd];
            acc += qq.x * kv.x + qq.y * kv.y + qq.z * kv.z + qq.w * kv.w
                 + gq.x * rv.x + gq.y * rv.y + gq.z * rv.z + gq.w * rv.w;
        }
        acc += __shfl_xor_sync(0xffffffffu, acc, 1);
        acc += __shfl_xor_sync(0xffffffffu, acc, 2);
        if (sub == 0 && valid) sc[qi * SP + k] = acc + msk[k];
    }
    __syncthreads();

    // ---- phase 2: softmax per row + probs write ----
    for (int qi = warp; qi < TQ; qi += 8) {
        float m = -1e30f;
        for (int j = lane; j < NS; j += 32) m = fmaxf(m, sc[qi * SP + j]);
#pragma unroll
        for (int o = 16; o; o >>= 1) m = fmaxf(m, __shfl_xor_sync(0xffffffffu, m, o));
        float sum = 0.f;
        for (int j = lane; j < NS; j += 32) {
            const float e = __expf(sc[qi * SP + j] - m);
            sc[qi * SP + j] = e;
            sum += e;
        }
#pragma unroll
        for (int o = 16; o; o >>= 1) sum += __shfl_xor_sync(0xffffffffu, sum, o);
        const float inv = 1.0f / sum;
        const size_t pb = ((size_t)bh * NS + q0 + qi) * NS;
        for (int j = lane; j < NS; j += 32) {
            const float p = sc[qi * SP + j] * inv;
            sc[qi * SP + j] = p;
            if (write_probs) out_probs[pb + j] = p;
        }
    }
    __syncthreads();

    // ---- phase 3: ctx = probs @ V ----
    // thread owns d = tid&63, qi subset {g, g+4, g+8, (g+12)}; V row broadcast.
    const int g = tid >> 6;      // 0..3
    const int d = tid & 63;
    const int nq = (g < 2) ? 4 : 3;
    const float* Vb = g_V + (size_t)bh * NS * NDH;

    float acc[4] = {0.f, 0.f, 0.f, 0.f};
#pragma unroll 4
    for (int k = 0; k < NS; ++k) {
        const float v = Vb[(size_t)k * NDH + d];
#pragma unroll
        for (int t = 0; t < 4; ++t)
            if (t < nq) acc[t] += sc[(g + 4 * t) * SP + k] * v;
    }
#pragma unroll
    for (int t = 0; t < 4; ++t) {
        if (t >= nq) break;
        const int qi = g + 4 * t;
        out_ctx[(((size_t)b * NS + q0 + qi) * NHEADS + h) * NDH + d] = acc[t];
    }
}

// ---------------------------------------------------------------------------
// Launch. Inputs: hidden, rpe, mask, Wq,bq, Wk,bk, Wv,bv, Wg,bg.
// Output = concat(ctx.flat, probs.flat); probs write guarded by out_size.
// ---------------------------------------------------------------------------
extern "C" void kernel_launch(void* const* d_in, const int* in_sizes, int n_in,
                              void* d_out, int out_size)
{
    const float* hidden = (const float*)d_in[0];
    const float* rpe    = (const float*)d_in[1];
    const float* mask   = (const float*)d_in[2];
    const float* Wq = (const float*)d_in[3];
    const float* bq = (const float*)d_in[4];
    const float* Wk = (const float*)d_in[5];
    const float* bk = (const float*)d_in[6];
    const float* Wv = (const float*)d_in[7];
    const float* bv = (const float*)d_in[8];
    const float* Wg = (const float*)d_in[9];
    const float* bg = (const float*)d_in[10];

    float* out = (float*)d_out;
    const size_t ctx_elems   = (size_t)NB * NS * NHID;          // 1,605,632
    const size_t probs_elems = (size_t)NB * NHEADS * NS * NS;   // 4,917,248
    const int write_probs = ((size_t)out_size >= ctx_elems + probs_elems) ? 1 : 0;
    float* out_probs = out + ctx_elems;

    proj_kernel<<<dim3(4, 25, 4), 256>>>(hidden, Wq, bq, Wk, bk, Wv, bv, Wg, bg);
    attn_kernel<<<dim3(NS / TQ, NHEADS, NB), 256>>>(
        rpe, mask, out, out_probs, write_probs);
}